// round 2
// baseline (speedup 1.0000x reference)
#include <cuda_runtime.h>
#include <cuda_bf16.h>
#include <cstdint>

// Problem dims (fixed by reference)
#define T_DIM 1024
#define B_DIM 32
#define K_DIM 8
#define N_DIM 64
#define M_DIM 64
#define KN    512      // K_DIM * N_DIM
#define BK    256      // B_DIM * K_DIM
#define TBKN  16384    // B_DIM * KN (stride per t in s3 scratch)

#define X_SZ   (T_DIM * B_DIM * K_DIM)   // 262144
#define C_SZ   (K_DIM * N_DIM * M_DIM)   // 32768
#define V_SZ   (K_DIM * N_DIM)           // 512  (lam_re/lam_im/D/Do)
#define OUT_CPLX (T_DIM * B_DIM * M_DIM) // 2097152 complex values

// ---------------- scratch (static device allocations only) ----------------
__device__ float2 g_Bp[KN];
__device__ float2 g_s3[(size_t)T_DIM * B_DIM * KN];   // [t][b][k*64+n], 128 MiB

// ---------------- packed f32x2 helpers (Blackwell) ----------------
__device__ __forceinline__ unsigned long long f32x2_fma(
        unsigned long long a, unsigned long long b, unsigned long long c) {
    unsigned long long d;
    asm("fma.rn.f32x2 %0, %1, %2, %3;" : "=l"(d) : "l"(a), "l"(b), "l"(c));
    return d;
}

__device__ __forceinline__ float2 u2f2(unsigned long long v) {
    float2 f;
    asm("mov.b64 {%0, %1}, %2;" : "=f"(f.x), "=f"(f.y) : "l"(v));
    return f;
}

union f4u { float4 f; ulonglong2 u; };

// ---------------- kernel 1: B' from lambda (exact, fp64) ----------------
// B'[k,j] = exp(-sum_{i != j} log(1 - lam_i/lam_j))   (complex, per k)
__global__ void bp_kernel(const float* __restrict__ lam_re,
                          const float* __restrict__ lam_im) {
    int idx = threadIdx.x;            // 0..511 == k*64 + j
    int j = idx & 63;
    int base = idx & ~63;             // k*64
    double ljr = lam_re[idx], lji = lam_im[idx];
    double den = ljr * ljr + lji * lji;
    double sr = 0.0, si = 0.0;
    for (int i = 0; i < N_DIM; ++i) {
        if (i == j) continue;
        double lir = lam_re[base + i], lii = lam_im[base + i];
        double rr = (lir * ljr + lii * lji) / den;   // (lam_i / lam_j).re
        double ri = (lii * ljr - lir * lji) / den;   // (lam_i / lam_j).im
        double wr = 1.0 - rr, wi = -ri;              // 1 - ratio
        sr += 0.5 * log(wr * wr + wi * wi);          // Re log
        si += atan2(wi, wr);                         // Im log
    }
    // Bp = exp(-(sr + i*si))
    double er = exp(-sr);
    g_Bp[idx] = make_float2((float)(er * cos(si)), (float)(-er * sin(si)));
}

// ---------------- kernel 2: fused 3-pass scan ----------------
// one block per (b,k); thread n owns state triple (s1,s2,s3) for mode n.
// s_t = a_{t-1} * lam * s_{t-1} + Bp * x_{t-1}   (s_0 = 0)
// pass1: a == 1;  pass2: a = rsqrt(1+|lam*s1|^2);  pass3: a = rsqrt(1+|lam*s2|^2)
__global__ __launch_bounds__(64) void scan_kernel(
        const float* __restrict__ x,
        const float* __restrict__ lam_re,
        const float* __restrict__ lam_im) {
    int bk = blockIdx.x;              // 0..255
    int b = bk >> 3;
    int k = bk & 7;
    int n = threadIdx.x;              // 0..63
    int kn = (k << 6) | n;

    float lr = lam_re[kn], li = lam_im[kn];
    float2 Bp = g_Bp[kn];
    float2 s1 = make_float2(0.f, 0.f);
    float2 s2 = make_float2(0.f, 0.f);
    float2 s3 = make_float2(0.f, 0.f);

    __shared__ float xs[64];
    const int xoff = b * K_DIM + k;
    float2* out = g_s3 + ((size_t)b * KN + kn);

    for (int tt = 0; tt < T_DIM; tt += 64) {
        __syncthreads();
        int tl = tt + n;                              // step index this thread stages x for
        xs[n] = (tl == 0) ? 0.f : x[(tl - 1) * BK + xoff];
        __syncthreads();
        #pragma unroll 8
        for (int j = 0; j < 64; ++j) {
            float xm1 = xs[j];
            float p1r = lr * s1.x - li * s1.y;
            float p1i = lr * s1.y + li * s1.x;
            float p2r = lr * s2.x - li * s2.y;
            float p2i = lr * s2.y + li * s2.x;
            float p3r = lr * s3.x - li * s3.y;
            float p3i = lr * s3.y + li * s3.x;
            float a1 = rsqrtf(1.f + p1r * p1r + p1i * p1i);   // from s1_{t-1}
            float a2 = rsqrtf(1.f + p2r * p2r + p2i * p2i);   // from s2_{t-1}
            float bxr = Bp.x * xm1, bxi = Bp.y * xm1;
            s3.x = fmaf(a2, p3r, bxr);  s3.y = fmaf(a2, p3i, bxi);
            s2.x = fmaf(a1, p2r, bxr);  s2.y = fmaf(a1, p2i, bxi);
            s1.x = p1r + bxr;           s1.y = p1i + bxi;
            out[(size_t)(tt + j) * TBKN] = s3;
        }
    }
}

// ---------------- kernel 3: complex GEMM + epilogue ----------------
// out[r=t*B+b][m] = ( sum_{kn} s3[r][kn] * Cp[kn][m] + sum_k x[t,b,k]*D[k,m] + sum_k Do[k,m] ) / 8
// block: 64-row tile x all 64 cols; 256 threads, 4x4 complex per thread.
// complex MAC via 2 packed fma.rn.f32x2:
//   (ar,ar)*(br,bi) + (-ai,ai)*(bi,br) = (re, im) contribution
#define KC 16

template <int WRITE_CPLX>
__global__ __launch_bounds__(256) void gemm_kernel(
        const float* __restrict__ C_re, const float* __restrict__ C_im,
        const float* __restrict__ x,    const float* __restrict__ D,
        const float* __restrict__ Do,   float* __restrict__ out) {
    __shared__ ulonglong2 AsU[KC][64];     // [(ar,ar),(-ai,ai)]
    __shared__ ulonglong2 BsU[KC][64];     // [(br,bi),(bi,br)]
    __shared__ float Ds[K_DIM][M_DIM];
    __shared__ float doSum[M_DIM];

    int tid = threadIdx.x;
    int rowBase = blockIdx.x * 64;

    // prologue: stage D and sum_k Do
    for (int idx = tid; idx < K_DIM * M_DIM; idx += 256)
        Ds[idx >> 6][idx & 63] = D[idx];
    if (tid < M_DIM) {
        float s = 0.f;
        #pragma unroll
        for (int k = 0; k < K_DIM; ++k) s += Do[k * M_DIM + tid];
        doSum[tid] = s;
    }

    int row0 = (tid >> 4) << 2;   // 0,4,...,60
    int col0 = (tid & 15) << 2;   // 0,4,...,60

    unsigned long long acc[4][4];
    #pragma unroll
    for (int i = 0; i < 4; ++i)
        #pragma unroll
        for (int j = 0; j < 4; ++j) acc[i][j] = 0ull;

    const float2* A = g_s3;

    for (int kk = 0; kk < KN; kk += KC) {
        __syncthreads();
        // A tile: 64 rows x KC inner
        #pragma unroll
        for (int i = 0; i < (64 * KC) / 256; ++i) {
            int idx = tid + i * 256;
            int r = idx >> 4;             // /KC
            int c = idx & (KC - 1);
            float2 g = A[(size_t)(rowBase + r) * KN + (kk + c)];
            f4u u; u.f = make_float4(g.x, g.x, -g.y, g.y);
            AsU[c][r] = u.u;
        }
        // B tile: KC inner x 64 cols
        #pragma unroll
        for (int i = 0; i < (64 * KC) / 256; ++i) {
            int idx = tid + i * 256;
            int c = idx >> 6;
            int m = idx & 63;
            float br = C_re[(kk + c) * M_DIM + m];
            float bi = C_im[(kk + c) * M_DIM + m];
            f4u u; u.f = make_float4(br, bi, bi, br);
            BsU[c][m] = u.u;
        }
        __syncthreads();

        #pragma unroll
        for (int c = 0; c < KC; ++c) {
            ulonglong2 av[4], bv[4];
            #pragma unroll
            for (int i = 0; i < 4; ++i) av[i] = AsU[c][row0 + i];
            #pragma unroll
            for (int j = 0; j < 4; ++j) bv[j] = BsU[c][col0 + j];
            #pragma unroll
            for (int i = 0; i < 4; ++i)
                #pragma unroll
                for (int j = 0; j < 4; ++j) {
                    acc[i][j] = f32x2_fma(av[i].x, bv[j].x, acc[i][j]);
                    acc[i][j] = f32x2_fma(av[i].y, bv[j].y, acc[i][j]);
                }
        }
    }

    // epilogue: + x*D + Do, mean over k (x1/8)
    #pragma unroll
    for (int i = 0; i < 4; ++i) {
        int r = rowBase + row0 + i;
        int t = r >> 5;                 // r = t*B + b, B = 32
        int b = r & 31;
        const float* xr = x + (t * B_DIM + b) * K_DIM;
        float xv[K_DIM];
        #pragma unroll
        for (int k = 0; k < K_DIM; ++k) xv[k] = xr[k];
        #pragma unroll
        for (int j = 0; j < 4; ++j) {
            int m = col0 + j;
            float dt = 0.f;
            #pragma unroll
            for (int k = 0; k < K_DIM; ++k) dt = fmaf(xv[k], Ds[k][m], dt);
            float2 a = u2f2(acc[i][j]);
            float re = (a.x + dt + doSum[m]) * 0.125f;
            float im = a.y * 0.125f;
            if (WRITE_CPLX) {
                // interleaved complex64 viewed as float32 pairs
                ((float2*)out)[(size_t)r * M_DIM + m] = make_float2(re, im);
            } else {
                out[(size_t)r * M_DIM + m] = re;   // real-only buffer
            }
        }
    }
}

// ---------------- launch ----------------
extern "C" void kernel_launch(void* const* d_in, const int* in_sizes, int n_in,
                              void* d_out, int out_size) {
    // Resolve inputs by size so a permuted metadata order cannot cause OOB:
    //   262144 -> x (unique)
    //   32768  -> C_re, C_im     (encounter order)
    //   512    -> lam_re, lam_im, D, Do (encounter order)
    const float* x = nullptr;
    const float* cbuf[2] = {nullptr, nullptr};
    const float* vbuf[4] = {nullptr, nullptr, nullptr, nullptr};
    int nc = 0, nv = 0;
    for (int i = 0; i < n_in; ++i) {
        int sz = in_sizes[i];
        const float* p = (const float*)d_in[i];
        if (sz == X_SZ) x = p;
        else if (sz == C_SZ) { if (nc < 2) cbuf[nc++] = p; }
        else if (sz == V_SZ) { if (nv < 4) vbuf[nv++] = p; }
    }
    if (!x || nc < 2 || nv < 4) return;   // unexpected shape set; do nothing (no UB)
    const float* C_re   = cbuf[0];
    const float* C_im   = cbuf[1];
    const float* lam_re = vbuf[0];
    const float* lam_im = vbuf[1];
    const float* D      = vbuf[2];
    const float* Do     = vbuf[3];

    bp_kernel<<<1, KN>>>(lam_re, lam_im);
    scan_kernel<<<BK, N_DIM>>>(x, lam_re, lam_im);

    if (out_size >= 2 * OUT_CPLX) {
        // complex64 viewed as interleaved float32 (16 MB buffer)
        gemm_kernel<1><<<(T_DIM * B_DIM) / 64, 256>>>(C_re, C_im, x, D, Do, (float*)d_out);
    } else {
        // real-only buffer (8 MB): write real part, never exceed out_size
        gemm_kernel<0><<<(T_DIM * B_DIM) / 64, 256>>>(C_re, C_im, x, D, Do, (float*)d_out);
    }
}

// round 4
// speedup vs baseline: 4.4545x; 4.4545x over previous
#include <cuda_runtime.h>
#include <cuda_bf16.h>
#include <cstdint>

// Problem dims (fixed by reference)
#define T_DIM 1024
#define B_DIM 32
#define K_DIM 8
#define N_DIM 64
#define M_DIM 64
#define KN    512      // K_DIM * N_DIM
#define BK    256      // B_DIM * K_DIM
#define ROWS  32768    // T*B rows of the big GEMM
#define KTOT  1024     // real K (re|im stacked)
#define NTOT  128      // output cols (re|im stacked)

#define X_SZ   (T_DIM * B_DIM * K_DIM)   // 262144
#define C_SZ   (K_DIM * N_DIM * M_DIM)   // 32768
#define V_SZ   (K_DIM * N_DIM)           // 512
#define OUT_CPLX (T_DIM * B_DIM * M_DIM) // 2097152 complex values

// ---------------- scratch (static device allocations only) ----------------
__device__ float2 g_Bp[KN];
__device__ __nv_bfloat16 g_Ahi[(size_t)ROWS * KTOT];   // 64 MiB
__device__ __nv_bfloat16 g_Alo[(size_t)ROWS * KTOT];   // 64 MiB
__device__ __nv_bfloat16 g_Bh[NTOT * KTOT];            // 256 KiB, [n][k] K-major
__device__ __nv_bfloat16 g_Bl[NTOT * KTOT];

// ---------------- PTX helpers (base sm_100 features only) ----------------
__device__ __forceinline__ uint32_t smem_u32(const void* p) {
    uint32_t a;
    asm("{ .reg .u64 t; cvta.to.shared.u64 t, %1; cvt.u32.u64 %0, t; }" : "=r"(a) : "l"(p));
    return a;
}
__device__ __forceinline__ void ldsm_x4(uint32_t& r0, uint32_t& r1, uint32_t& r2,
                                        uint32_t& r3, uint32_t addr) {
    asm volatile("ldmatrix.sync.aligned.m8n8.x4.shared.b16 {%0,%1,%2,%3}, [%4];"
                 : "=r"(r0), "=r"(r1), "=r"(r2), "=r"(r3) : "r"(addr));
}
__device__ __forceinline__ void ldsm_x2(uint32_t& r0, uint32_t& r1, uint32_t addr) {
    asm volatile("ldmatrix.sync.aligned.m8n8.x2.shared.b16 {%0,%1}, [%2];"
                 : "=r"(r0), "=r"(r1) : "r"(addr));
}
__device__ __forceinline__ void mma_bf16(float* d, const uint32_t* a, const uint32_t* b) {
    asm volatile("mma.sync.aligned.m16n8k16.row.col.f32.bf16.bf16.f32 "
                 "{%0,%1,%2,%3}, {%4,%5,%6,%7}, {%8,%9}, {%0,%1,%2,%3};"
                 : "+f"(d[0]), "+f"(d[1]), "+f"(d[2]), "+f"(d[3])
                 : "r"(a[0]), "r"(a[1]), "r"(a[2]), "r"(a[3]), "r"(b[0]), "r"(b[1]));
}

// ---------------- kernel 1: B' from lambda (exact, fp64, parallel) --------
__global__ void bp_kernel(const float* __restrict__ lam_re,
                          const float* __restrict__ lam_im) {
    __shared__ double ssr[64], ssi[64];
    int idx = blockIdx.x;             // k*64 + j
    int j = idx & 63;
    int base = idx & ~63;
    int i = threadIdx.x;
    double sr = 0.0, si = 0.0;
    if (i != j) {
        double ljr = lam_re[idx], lji = lam_im[idx];
        double den = ljr * ljr + lji * lji;
        double lir = lam_re[base + i], lii = lam_im[base + i];
        double rr = (lir * ljr + lii * lji) / den;
        double ri = (lii * ljr - lir * lji) / den;
        double wr = 1.0 - rr, wi = -ri;
        sr = 0.5 * log(wr * wr + wi * wi);
        si = atan2(wi, wr);
    }
    ssr[i] = sr; ssi[i] = si;
    __syncthreads();
    #pragma unroll
    for (int s = 32; s > 0; s >>= 1) {
        if (i < s) { ssr[i] += ssr[i + s]; ssi[i] += ssi[i + s]; }
        __syncthreads();
    }
    if (i == 0) {
        double er = exp(-ssr[0]);
        g_Bp[idx] = make_float2((float)(er * cos(ssi[0])), (float)(-er * sin(ssi[0])));
    }
}

// ---------------- kernel 1b: stacked B operand (bf16 hi/lo, [n][k]) -------
//   n<64 (m=n):   k<512 -> C_re[k][m],  k>=512 -> -C_im[k-512][m]
//   n>=64(m=n-64):k<512 -> C_im[k][m],  k>=512 ->  C_re[k-512][m]
__global__ void bprep_kernel(const float* __restrict__ C_re,
                             const float* __restrict__ C_im) {
    int id = blockIdx.x * 256 + threadIdx.x;   // n*1024 + kk
    int n = id >> 10;
    int kk = id & 1023;
    int m = (n < 64) ? n : (n - 64);
    float v;
    if (kk < 512) v = (n < 64) ? C_re[kk * 64 + m] : C_im[kk * 64 + m];
    else {
        int k2 = kk - 512;
        v = (n < 64) ? -C_im[k2 * 64 + m] : C_re[k2 * 64 + m];
    }
    __nv_bfloat16 h = __float2bfloat16(v);
    g_Bh[id] = h;
    g_Bl[id] = __float2bfloat16(v - __bfloat162float(h));
}

// ---------------- kernel 2: fused 3-pass scan, bf16-split output ----------
__global__ __launch_bounds__(64) void scan_kernel(
        const float* __restrict__ x,
        const float* __restrict__ lam_re,
        const float* __restrict__ lam_im) {
    int bk = blockIdx.x;              // 0..255
    int b = bk >> 3;
    int k = bk & 7;
    int n = threadIdx.x;              // 0..63
    int kn = (k << 6) | n;

    float lr = lam_re[kn], li = lam_im[kn];
    float2 Bp = g_Bp[kn];
    float2 s1 = make_float2(0.f, 0.f);
    float2 s2 = make_float2(0.f, 0.f);
    float2 s3 = make_float2(0.f, 0.f);

    __shared__ float xs[64];
    const int xoff = b * K_DIM + k;

    for (int tt = 0; tt < T_DIM; tt += 64) {
        __syncthreads();
        int tl = tt + n;
        xs[n] = (tl == 0) ? 0.f : x[(tl - 1) * BK + xoff];
        __syncthreads();
        #pragma unroll 8
        for (int j = 0; j < 64; ++j) {
            float xm1 = xs[j];
            float p1r = lr * s1.x - li * s1.y;
            float p1i = lr * s1.y + li * s1.x;
            float p2r = lr * s2.x - li * s2.y;
            float p2i = lr * s2.y + li * s2.x;
            float p3r = lr * s3.x - li * s3.y;
            float p3i = lr * s3.y + li * s3.x;
            float a1 = rsqrtf(1.f + p1r * p1r + p1i * p1i);
            float a2 = rsqrtf(1.f + p2r * p2r + p2i * p2i);
            float bxr = Bp.x * xm1, bxi = Bp.y * xm1;
            s3.x = fmaf(a2, p3r, bxr);  s3.y = fmaf(a2, p3i, bxi);
            s2.x = fmaf(a1, p2r, bxr);  s2.y = fmaf(a1, p2i, bxi);
            s1.x = p1r + bxr;           s1.y = p1i + bxi;
            size_t ro = (((size_t)(tt + j) << 5) + b) * KTOT + kn;
            __nv_bfloat16 hre = __float2bfloat16(s3.x);
            __nv_bfloat16 him = __float2bfloat16(s3.y);
            g_Ahi[ro]       = hre;
            g_Ahi[ro + 512] = him;
            g_Alo[ro]       = __float2bfloat16(s3.x - __bfloat162float(hre));
            g_Alo[ro + 512] = __float2bfloat16(s3.y - __bfloat162float(him));
        }
    }
}

// ---------------- kernel 3: mma.sync bf16 GEMM + epilogue -----------------
// CTA 256 thr (8 warps, 4m x 2n), tile 128x128, warp tile 32x64.
// Split-bf16: acc += Ah*Bh + Al*Bh + Ah*Bl, fused per 32-wide k chunk.
// Smem rows padded to 80B -> ldmatrix conflict-free (r*80 mod 128 distinct).
#define SROW 80

__global__ __launch_bounds__(256, 2) void gemm_mma(
        const float* __restrict__ x, const float* __restrict__ D,
        const float* __restrict__ Do, float* __restrict__ out, int writeCplx) {
    __shared__ __align__(16) uint8_t sAh[128 * SROW];
    __shared__ __align__(16) uint8_t sAl[128 * SROW];
    __shared__ __align__(16) uint8_t sBh[128 * SROW];
    __shared__ __align__(16) uint8_t sBl[128 * SROW];
    __shared__ float Ds[512];
    __shared__ float doSum[64];

    int tid = threadIdx.x;
    int wid = tid >> 5, lane = tid & 31;
    int wm = wid & 3, wn = wid >> 2;          // warp grid 4m x 2n
    int rowBase = blockIdx.x * 128;

    for (int i = tid; i < 512; i += 256) Ds[i] = D[i];
    if (tid < 64) {
        float s = 0.f;
        #pragma unroll
        for (int k = 0; k < K_DIM; ++k) s += Do[k * 64 + tid];
        doSum[tid] = s;
    }

    // ldmatrix addresses (per-thread, fixed across chunks)
    uint32_t ah_base = smem_u32(sAh), al_base = smem_u32(sAl);
    uint32_t bh_base = smem_u32(sBh), bl_base = smem_u32(sBl);
    int mi = lane >> 3;                        // 0..3 (x4 matrix id)
    int arow = (lane & 7) + (mi & 1) * 8;      // within m16 tile
    int acol16 = mi >> 1;                      // 0/1 -> k0-7 / k8-15
    int bmi = (lane >> 3) & 1;                 // x2 matrix id (threads 0-15)
    int brow = lane & 7;

    float acc[2][8][4];
    #pragma unroll
    for (int mt = 0; mt < 2; ++mt)
        #pragma unroll
        for (int nt = 0; nt < 8; ++nt)
            #pragma unroll
            for (int e = 0; e < 4; ++e) acc[mt][nt][e] = 0.f;

    // gmem->smem load indices: idx = tid + i*256 -> row = idx/4, c = idx%4
    int grow = tid >> 2, gc = tid & 3;

    #pragma unroll 1
    for (int kc = 0; kc < 32; ++kc) {
        int k0 = kc * 32;
        __syncthreads();
        #pragma unroll
        for (int i = 0; i < 2; ++i) {
            int row = grow + i * 64;
            size_t ga = ((size_t)(rowBase + row)) * KTOT + k0 + gc * 8;
            size_t gb = ((size_t)row) * KTOT + k0 + gc * 8;
            uint32_t so = row * SROW + gc * 16;
            *(uint4*)(sAh + so) = *(const uint4*)(g_Ahi + ga);
            *(uint4*)(sAl + so) = *(const uint4*)(g_Alo + ga);
            *(uint4*)(sBh + so) = *(const uint4*)(g_Bh + gb);
            *(uint4*)(sBl + so) = *(const uint4*)(g_Bl + gb);
        }
        __syncthreads();

        #pragma unroll
        for (int ks = 0; ks < 2; ++ks) {
            // A fragments for both m16 tiles, hi and lo
            uint32_t ah[2][4], al[2][4];
            #pragma unroll
            for (int mt = 0; mt < 2; ++mt) {
                uint32_t off = (wm * 32 + mt * 16 + arow) * SROW + (ks * 2 + acol16) * 16;
                ldsm_x4(ah[mt][0], ah[mt][1], ah[mt][2], ah[mt][3], ah_base + off);
                ldsm_x4(al[mt][0], al[mt][1], al[mt][2], al[mt][3], al_base + off);
            }
            #pragma unroll
            for (int nt = 0; nt < 8; ++nt) {
                uint32_t boff = (wn * 64 + nt * 8 + brow) * SROW + (ks * 2 + bmi) * 16;
                uint32_t bh[2], bl[2];
                ldsm_x2(bh[0], bh[1], bh_base + boff);
                ldsm_x2(bl[0], bl[1], bl_base + boff);
                #pragma unroll
                for (int mt = 0; mt < 2; ++mt) {
                    mma_bf16(acc[mt][nt], ah[mt], bh);
                    mma_bf16(acc[mt][nt], al[mt], bh);
                    mma_bf16(acc[mt][nt], ah[mt], bl);
                }
            }
        }
    }
    __syncthreads();

    // epilogue
    int gID = lane >> 2, tg = lane & 3;
    #pragma unroll
    for (int mt = 0; mt < 2; ++mt) {
        #pragma unroll
        for (int half = 0; half < 2; ++half) {
            int R = rowBase + wm * 32 + mt * 16 + gID + half * 8;
            float xv[K_DIM];
            #pragma unroll
            for (int k = 0; k < K_DIM; ++k) xv[k] = x[R * K_DIM + k];
            #pragma unroll
            for (int nt = 0; nt < 8; ++nt) {
                #pragma unroll
                for (int e = 0; e < 2; ++e) {
                    int col = wn * 64 + nt * 8 + tg * 2 + e;
                    float a = acc[mt][nt][half * 2 + e];
                    if (wn == 0) {  // real part: add x*D + Do, scale
                        int m = col;
                        float dt = doSum[m];
                        #pragma unroll
                        for (int k = 0; k < K_DIM; ++k)
                            dt = fmaf(xv[k], Ds[k * 64 + m], dt);
                        float v = (a + dt) * 0.125f;
                        if (writeCplx) out[((size_t)R * 64 + m) * 2] = v;
                        else           out[(size_t)R * 64 + m] = v;
                    } else {        // imag part
                        int m = col - 64;
                        if (writeCplx) out[((size_t)R * 64 + m) * 2 + 1] = a * 0.125f;
                    }
                }
            }
        }
    }
}

// ---------------- launch ----------------
extern "C" void kernel_launch(void* const* d_in, const int* in_sizes, int n_in,
                              void* d_out, int out_size) {
    const float* x = nullptr;
    const float* cbuf[2] = {nullptr, nullptr};
    const float* vbuf[4] = {nullptr, nullptr, nullptr, nullptr};
    int nc = 0, nv = 0;
    for (int i = 0; i < n_in; ++i) {
        int sz = in_sizes[i];
        const float* p = (const float*)d_in[i];
        if (sz == X_SZ) x = p;
        else if (sz == C_SZ) { if (nc < 2) cbuf[nc++] = p; }
        else if (sz == V_SZ) { if (nv < 4) vbuf[nv++] = p; }
    }
    if (!x || nc < 2 || nv < 4) return;
    const float* C_re   = cbuf[0];
    const float* C_im   = cbuf[1];
    const float* lam_re = vbuf[0];
    const float* lam_im = vbuf[1];
    const float* D      = vbuf[2];
    const float* Do     = vbuf[3];

    int writeCplx = (out_size >= 2 * OUT_CPLX) ? 1 : 0;

    bp_kernel<<<KN, 64>>>(lam_re, lam_im);
    bprep_kernel<<<512, 256>>>(C_re, C_im);
    scan_kernel<<<BK, N_DIM>>>(x, lam_re, lam_im);
    gemm_mma<<<ROWS / 128, 256>>>(x, D, Do, (float*)d_out, writeCplx);
}

// round 5
// speedup vs baseline: 4.6741x; 1.0493x over previous
#include <cuda_runtime.h>
#include <cuda_bf16.h>
#include <cstdint>

// Problem dims (fixed by reference)
#define T_DIM 1024
#define B_DIM 32
#define K_DIM 8
#define N_DIM 64
#define M_DIM 64
#define KN    512      // K_DIM * N_DIM
#define BK    256      // B_DIM * K_DIM
#define ROWS  32768    // T*B rows of the big GEMM
#define KTOT  1024     // real K (re|im interleaved: kk=2p -> re, 2p+1 -> im)
#define NTOT  128      // output cols (re|im stacked)

#define X_SZ   (T_DIM * B_DIM * K_DIM)   // 262144
#define C_SZ   (K_DIM * N_DIM * M_DIM)   // 32768
#define V_SZ   (K_DIM * N_DIM)           // 512
#define OUT_CPLX (T_DIM * B_DIM * M_DIM) // 2097152 complex values

// ---------------- scratch (static device allocations only) ----------------
__device__ float2   g_Bp[KN];
__device__ uint32_t g_Ahi[(size_t)ROWS * 512];   // 64 MiB, packed bf16x2 (re,im)
__device__ uint32_t g_Alo[(size_t)ROWS * 512];   // 64 MiB
__device__ uint32_t g_Bh[NTOT * 512];            // 256 KiB, [n][kk] K-major packed
__device__ uint32_t g_Bl[NTOT * 512];

// ---------------- PTX helpers (base sm_100 features only) ----------------
__device__ __forceinline__ uint32_t smem_u32(const void* p) {
    uint32_t a;
    asm("{ .reg .u64 t; cvta.to.shared.u64 t, %1; cvt.u32.u64 %0, t; }" : "=r"(a) : "l"(p));
    return a;
}
__device__ __forceinline__ void ldsm_x4(uint32_t* r, uint32_t addr) {
    asm volatile("ldmatrix.sync.aligned.m8n8.x4.shared.b16 {%0,%1,%2,%3}, [%4];"
                 : "=r"(r[0]), "=r"(r[1]), "=r"(r[2]), "=r"(r[3]) : "r"(addr));
}
__device__ __forceinline__ void mma_bf16(float* d, const uint32_t* a, const uint32_t* b) {
    asm volatile("mma.sync.aligned.m16n8k16.row.col.f32.bf16.bf16.f32 "
                 "{%0,%1,%2,%3}, {%4,%5,%6,%7}, {%8,%9}, {%0,%1,%2,%3};"
                 : "+f"(d[0]), "+f"(d[1]), "+f"(d[2]), "+f"(d[3])
                 : "r"(a[0]), "r"(a[1]), "r"(a[2]), "r"(a[3]), "r"(b[0]), "r"(b[1]));
}
#define CP16(dst, src) \
    asm volatile("cp.async.cg.shared.global [%0], [%1], 16;" :: "r"(dst), "l"(src))
#define CP_COMMIT() asm volatile("cp.async.commit_group;" ::: "memory")
#define CP_WAIT(n)  asm volatile("cp.async.wait_group %0;" :: "n"(n) : "memory")

__device__ __forceinline__ uint32_t pack_bf16x2(float lo, float hi) {
    uint32_t r;
    asm("cvt.rn.bf16x2.f32 %0, %1, %2;" : "=r"(r) : "f"(hi), "f"(lo));
    return r;
}

// ---------------- kernel 1: B' from lambda (fp32, parallel) ---------------
// block idx = k*64+j; 64 threads, one off-diagonal term each; smem reduce.
__global__ void bp_kernel(const float* __restrict__ lam_re,
                          const float* __restrict__ lam_im) {
    __shared__ float ssr[64], ssi[64];
    int idx = blockIdx.x;
    int j = idx & 63;
    int base = idx & ~63;
    int i = threadIdx.x;
    float sr = 0.f, si = 0.f;
    if (i != j) {
        float ljr = lam_re[idx], lji = lam_im[idx];
        float den = ljr * ljr + lji * lji;
        float lir = lam_re[base + i], lii = lam_im[base + i];
        float rr = (lir * ljr + lii * lji) / den;
        float ri = (lii * ljr - lir * lji) / den;
        float wr = 1.f - rr, wi = -ri;
        sr = 0.5f * logf(wr * wr + wi * wi);
        si = atan2f(wi, wr);
    }
    ssr[i] = sr; ssi[i] = si;
    __syncthreads();
    #pragma unroll
    for (int s = 32; s > 0; s >>= 1) {
        if (i < s) { ssr[i] += ssr[i + s]; ssi[i] += ssi[i + s]; }
        __syncthreads();
    }
    if (i == 0) {
        float er = expf(-ssr[0]);
        float sn, cs; sincosf(ssi[0], &sn, &cs);
        g_Bp[idx] = make_float2(er * cs, -er * sn);
    }
}

// ---------------- kernel 1b: stacked B (bf16 hi/lo, packed pairs) ---------
// B[n][2p]   : n<64 -> C_re[p][n],     n>=64 -> C_im[p][n-64]
// B[n][2p+1] : n<64 -> -C_im[p][n],    n>=64 -> C_re[p][n-64]
__global__ void bprep_kernel(const float* __restrict__ C_re,
                             const float* __restrict__ C_im) {
    int id = blockIdx.x * 256 + threadIdx.x;   // n*512 + p (uint32 col)
    int n = id >> 9;
    int p = id & 511;
    int m = n & 63;
    float v0, v1;
    if (n < 64) { v0 = C_re[p * 64 + m]; v1 = -C_im[p * 64 + m]; }
    else        { v0 = C_im[p * 64 + m]; v1 =  C_re[p * 64 + m]; }
    uint32_t h = pack_bf16x2(v0, v1);
    float h0 = __uint_as_float(h << 16);
    float h1 = __uint_as_float(h & 0xFFFF0000u);
    g_Bh[id] = h;
    g_Bl[id] = pack_bf16x2(v0 - h0, v1 - h1);
}

// ---------------- kernel 2: fused 3-pass scan, packed bf16 output ---------
__global__ __launch_bounds__(64) void scan_kernel(
        const float* __restrict__ x,
        const float* __restrict__ lam_re,
        const float* __restrict__ lam_im) {
    int bk = blockIdx.x;              // 0..255
    int b = bk >> 3;
    int k = bk & 7;
    int n = threadIdx.x;              // 0..63
    int kn = (k << 6) | n;

    float lr = lam_re[kn], li = lam_im[kn];
    float2 Bp = g_Bp[kn];
    float2 s1 = make_float2(0.f, 0.f);
    float2 s2 = make_float2(0.f, 0.f);
    float2 s3 = make_float2(0.f, 0.f);

    __shared__ float xs[64];
    const int xoff = b * K_DIM + k;

    for (int tt = 0; tt < T_DIM; tt += 64) {
        __syncthreads();
        int tl = tt + n;
        xs[n] = (tl == 0) ? 0.f : x[(tl - 1) * BK + xoff];
        __syncthreads();
        #pragma unroll 8
        for (int j = 0; j < 64; ++j) {
            float xm1 = xs[j];
            float p1r = lr * s1.x - li * s1.y;
            float p1i = lr * s1.y + li * s1.x;
            float p2r = lr * s2.x - li * s2.y;
            float p2i = lr * s2.y + li * s2.x;
            float p3r = lr * s3.x - li * s3.y;
            float p3i = lr * s3.y + li * s3.x;
            float a1 = rsqrtf(1.f + p1r * p1r + p1i * p1i);
            float a2 = rsqrtf(1.f + p2r * p2r + p2i * p2i);
            float bxr = Bp.x * xm1, bxi = Bp.y * xm1;
            s3.x = fmaf(a2, p3r, bxr);  s3.y = fmaf(a2, p3i, bxi);
            s2.x = fmaf(a1, p2r, bxr);  s2.y = fmaf(a1, p2i, bxi);
            s1.x = p1r + bxr;           s1.y = p1i + bxi;
            uint32_t ro = (((tt + j) << 5) + b) * 512 + kn;
            uint32_t h = pack_bf16x2(s3.x, s3.y);
            float hre = __uint_as_float(h << 16);
            float him = __uint_as_float(h & 0xFFFF0000u);
            g_Ahi[ro] = h;
            g_Alo[ro] = pack_bf16x2(s3.x - hre, s3.y - him);
        }
    }
}

// ---------------- kernel 3: mma.sync bf16 GEMM, cp.async 2-stage ----------
// CTA 256 thr (8 warps, 4m x 2n), tile 128x128, warp tile 32x64.
// acc += Ah*Bh + Al*Bh + Ah*Bl per 32-wide k chunk (fused).
#define SROW 80
#define STAGE_BYTES (4 * 128 * SROW)   // Ah,Al,Bh,Bl tiles = 40960
#define NCHUNK 32

extern __shared__ uint8_t dynSmem[];

__device__ __forceinline__ void issue_chunk(int kc, uint32_t sbuf, int rowBase,
                                            int grow, int gc) {
    int k0 = kc * 32;   // bf16 elems
    const uint8_t* gAh = (const uint8_t*)g_Ahi;
    const uint8_t* gAl = (const uint8_t*)g_Alo;
    const uint8_t* gBh = (const uint8_t*)g_Bh;
    const uint8_t* gBl = (const uint8_t*)g_Bl;
    #pragma unroll
    for (int i = 0; i < 2; ++i) {
        int row = grow + i * 64;
        size_t ga = ((size_t)(rowBase + row) * KTOT + k0) * 2 + gc * 16;
        size_t gb = ((size_t)row * KTOT + k0) * 2 + gc * 16;
        uint32_t so = row * SROW + gc * 16;
        CP16(sbuf + so,                   gAh + ga);
        CP16(sbuf + 10240 + so,           gAl + ga);
        CP16(sbuf + 20480 + so,           gBh + gb);
        CP16(sbuf + 30720 + so,           gBl + gb);
    }
}

__global__ __launch_bounds__(256, 2) void gemm_mma(
        const float* __restrict__ x, const float* __restrict__ D,
        const float* __restrict__ Do, float* __restrict__ out, int writeCplx) {
    __shared__ float Ds[512];
    __shared__ float doSum[64];

    int tid = threadIdx.x;
    int wid = tid >> 5, lane = tid & 31;
    int wm = wid & 3, wn = wid >> 2;          // warp grid 4m x 2n
    int rowBase = blockIdx.x * 128;

    for (int i = tid; i < 512; i += 256) Ds[i] = D[i];
    if (tid < 64) {
        float s = 0.f;
        #pragma unroll
        for (int k = 0; k < K_DIM; ++k) s += Do[k * 64 + tid];
        doSum[tid] = s;
    }

    uint32_t sbase0 = smem_u32(dynSmem);
    uint32_t sbase[2] = { sbase0, sbase0 + STAGE_BYTES };

    // ldmatrix per-thread address components
    int mi = lane >> 3;                        // 0..3
    int arow = (lane & 7) + (mi & 1) * 8;      // A: m0 rows0-7 k0, m1 rows8-15 k0, m2 r0-7 k8, m3 r8-15 k8
    int acol16 = mi >> 1;
    int bnrow = (mi >> 1) * 8 + (lane & 7);    // B x4: m0 n0-7 k0, m1 n0-7 k8, m2 n8-15 k0, m3 n8-15 k8
    int bk16 = mi & 1;

    float acc[2][8][4];
    #pragma unroll
    for (int mt = 0; mt < 2; ++mt)
        #pragma unroll
        for (int nt = 0; nt < 8; ++nt)
            #pragma unroll
            for (int e = 0; e < 4; ++e) acc[mt][nt][e] = 0.f;

    int grow = tid >> 2, gc = tid & 3;

    issue_chunk(0, sbase[0], rowBase, grow, gc);
    CP_COMMIT();

    #pragma unroll 1
    for (int kc = 0; kc < NCHUNK; ++kc) {
        if (kc + 1 < NCHUNK) {
            issue_chunk(kc + 1, sbase[(kc + 1) & 1], rowBase, grow, gc);
            CP_COMMIT();
            CP_WAIT(1);
        } else {
            CP_WAIT(0);
        }
        __syncthreads();

        uint32_t sAh = sbase[kc & 1];
        uint32_t sAl = sAh + 10240;
        uint32_t sBh = sAh + 20480;
        uint32_t sBl = sAh + 30720;

        #pragma unroll
        for (int ks = 0; ks < 2; ++ks) {
            uint32_t ah[2][4], al[2][4];
            #pragma unroll
            for (int mt = 0; mt < 2; ++mt) {
                uint32_t off = (wm * 32 + mt * 16 + arow) * SROW + (ks * 2 + acol16) * 16;
                ldsm_x4(ah[mt], sAh + off);
                ldsm_x4(al[mt], sAl + off);
            }
            #pragma unroll
            for (int ntp = 0; ntp < 4; ++ntp) {
                uint32_t boff = (wn * 64 + ntp * 16 + bnrow) * SROW + ks * 32 + bk16 * 16;
                uint32_t bh4[4], bl4[4];
                ldsm_x4(bh4, sBh + boff);
                ldsm_x4(bl4, sBl + boff);
                #pragma unroll
                for (int mt = 0; mt < 2; ++mt) {
                    mma_bf16(acc[mt][2 * ntp],     ah[mt], bh4);
                    mma_bf16(acc[mt][2 * ntp],     al[mt], bh4);
                    mma_bf16(acc[mt][2 * ntp],     ah[mt], bl4);
                    mma_bf16(acc[mt][2 * ntp + 1], ah[mt], bh4 + 2);
                    mma_bf16(acc[mt][2 * ntp + 1], al[mt], bh4 + 2);
                    mma_bf16(acc[mt][2 * ntp + 1], ah[mt], bl4 + 2);
                }
            }
        }
        __syncthreads();
    }

    // epilogue
    int gID = lane >> 2, tg = lane & 3;
    #pragma unroll
    for (int mt = 0; mt < 2; ++mt) {
        #pragma unroll
        for (int half = 0; half < 2; ++half) {
            int R = rowBase + wm * 32 + mt * 16 + gID + half * 8;
            float xv[K_DIM];
            #pragma unroll
            for (int k = 0; k < K_DIM; ++k) xv[k] = x[R * K_DIM + k];
            #pragma unroll
            for (int nt = 0; nt < 8; ++nt) {
                #pragma unroll
                for (int e = 0; e < 2; ++e) {
                    int col = wn * 64 + nt * 8 + tg * 2 + e;
                    float a = acc[mt][nt][half * 2 + e];
                    if (wn == 0) {  // real part: add x*D + Do, scale
                        int m = col;
                        float dt = doSum[m];
                        #pragma unroll
                        for (int k = 0; k < K_DIM; ++k)
                            dt = fmaf(xv[k], Ds[k * 64 + m], dt);
                        float v = (a + dt) * 0.125f;
                        if (writeCplx) out[((size_t)R * 64 + m) * 2] = v;
                        else           out[(size_t)R * 64 + m] = v;
                    } else {        // imag part
                        int m = col - 64;
                        if (writeCplx) out[((size_t)R * 64 + m) * 2 + 1] = a * 0.125f;
                    }
                }
            }
        }
    }
}

// ---------------- launch ----------------
extern "C" void kernel_launch(void* const* d_in, const int* in_sizes, int n_in,
                              void* d_out, int out_size) {
    const float* x = nullptr;
    const float* cbuf[2] = {nullptr, nullptr};
    const float* vbuf[4] = {nullptr, nullptr, nullptr, nullptr};
    int nc = 0, nv = 0;
    for (int i = 0; i < n_in; ++i) {
        int sz = in_sizes[i];
        const float* p = (const float*)d_in[i];
        if (sz == X_SZ) x = p;
        else if (sz == C_SZ) { if (nc < 2) cbuf[nc++] = p; }
        else if (sz == V_SZ) { if (nv < 4) vbuf[nv++] = p; }
    }
    if (!x || nc < 2 || nv < 4) return;
    const float* C_re   = cbuf[0];
    const float* C_im   = cbuf[1];
    const float* lam_re = vbuf[0];
    const float* lam_im = vbuf[1];
    const float* D      = vbuf[2];
    const float* Do     = vbuf[3];

    int writeCplx = (out_size >= 2 * OUT_CPLX) ? 1 : 0;

    static bool attrDone = false;
    if (!attrDone) {
        cudaFuncSetAttribute(gemm_mma, cudaFuncAttributeMaxDynamicSharedMemorySize,
                             2 * STAGE_BYTES);
        attrDone = true;
    }

    bp_kernel<<<KN, 64>>>(lam_re, lam_im);
    bprep_kernel<<<NTOT * 512 / 256, 256>>>(C_re, C_im);
    scan_kernel<<<BK, N_DIM>>>(x, lam_re, lam_im);
    gemm_mma<<<ROWS / 128, 256, 2 * STAGE_BYTES>>>(x, D, Do, (float*)d_out, writeCplx);
}

// round 7
// speedup vs baseline: 5.4748x; 1.1713x over previous
#include <cuda_runtime.h>
#include <cuda_bf16.h>
#include <cstdint>

// Problem dims (fixed by reference)
#define T_DIM 1024
#define B_DIM 32
#define K_DIM 8
#define N_DIM 64
#define M_DIM 64
#define KN    512      // K_DIM * N_DIM
#define BK    256      // B_DIM * K_DIM
#define ROWS  32768    // T*B rows of the big GEMM
#define KTOT  1024     // real K (re|im interleaved: kk=2p -> re, 2p+1 -> im)
#define NTOT  128      // output cols (re|im stacked)

#define X_SZ   (T_DIM * B_DIM * K_DIM)   // 262144
#define C_SZ   (K_DIM * N_DIM * M_DIM)   // 32768
#define V_SZ   (K_DIM * N_DIM)           // 512
#define OUT_CPLX (T_DIM * B_DIM * M_DIM) // 2097152 complex values

// ---------------- scratch (static device allocations only) ----------------
__device__ float2   g_Bp[KN];
__device__ uint32_t g_Ahi[(size_t)ROWS * 512];   // 64 MiB, packed bf16x2 (re,im)
__device__ uint32_t g_Alo[(size_t)ROWS * 512];   // 64 MiB
__device__ uint32_t g_Bh[NTOT * 512];            // 256 KiB, [n][kk] K-major packed
__device__ uint32_t g_Bl[NTOT * 512];

// ---------------- PTX helpers (base sm_100 features only) ----------------
__device__ __forceinline__ uint32_t smem_u32(const void* p) {
    uint32_t a;
    asm("{ .reg .u64 t; cvta.to.shared.u64 t, %1; cvt.u32.u64 %0, t; }" : "=r"(a) : "l"(p));
    return a;
}
__device__ __forceinline__ void ldsm_x4(uint32_t* r, uint32_t addr) {
    asm volatile("ldmatrix.sync.aligned.m8n8.x4.shared.b16 {%0,%1,%2,%3}, [%4];"
                 : "=r"(r[0]), "=r"(r[1]), "=r"(r[2]), "=r"(r[3]) : "r"(addr));
}
__device__ __forceinline__ void mma_bf16(float* d, const uint32_t* a, const uint32_t* b) {
    asm volatile("mma.sync.aligned.m16n8k16.row.col.f32.bf16.bf16.f32 "
                 "{%0,%1,%2,%3}, {%4,%5,%6,%7}, {%8,%9}, {%0,%1,%2,%3};"
                 : "+f"(d[0]), "+f"(d[1]), "+f"(d[2]), "+f"(d[3])
                 : "r"(a[0]), "r"(a[1]), "r"(a[2]), "r"(a[3]), "r"(b[0]), "r"(b[1]));
}
#define CP16(dst, src) \
    asm volatile("cp.async.cg.shared.global [%0], [%1], 16;" :: "r"(dst), "l"(src))
#define CP_COMMIT() asm volatile("cp.async.commit_group;" ::: "memory")
#define CP_WAIT(n)  asm volatile("cp.async.wait_group %0;" :: "n"(n) : "memory")

__device__ __forceinline__ uint32_t pack_bf16x2(float lo, float hi) {
    uint32_t r;
    asm("cvt.rn.bf16x2.f32 %0, %1, %2;" : "=r"(r) : "f"(hi), "f"(lo));
    return r;
}

// ---------------- kernel 1: B' from lambda (fp32, parallel) ---------------
__global__ void bp_kernel(const float* __restrict__ lam_re,
                          const float* __restrict__ lam_im) {
    __shared__ float ssr[64], ssi[64];
    int idx = blockIdx.x;
    int j = idx & 63;
    int base = idx & ~63;
    int i = threadIdx.x;
    float sr = 0.f, si = 0.f;
    if (i != j) {
        float ljr = lam_re[idx], lji = lam_im[idx];
        float den = ljr * ljr + lji * lji;
        float lir = lam_re[base + i], lii = lam_im[base + i];
        float rr = (lir * ljr + lii * lji) / den;
        float ri = (lii * ljr - lir * lji) / den;
        float wr = 1.f - rr, wi = -ri;
        sr = 0.5f * logf(wr * wr + wi * wi);
        si = atan2f(wi, wr);
    }
    ssr[i] = sr; ssi[i] = si;
    __syncthreads();
    #pragma unroll
    for (int s = 32; s > 0; s >>= 1) {
        if (i < s) { ssr[i] += ssr[i + s]; ssi[i] += ssi[i + s]; }
        __syncthreads();
    }
    if (i == 0) {
        float er = expf(-ssr[0]);
        float sn, cs; sincosf(ssi[0], &sn, &cs);
        g_Bp[idx] = make_float2(er * cs, -er * sn);
    }
}

// ---------------- kernel 1b: stacked B (bf16 hi/lo, packed pairs) ---------
__global__ void bprep_kernel(const float* __restrict__ C_re,
                             const float* __restrict__ C_im) {
    int id = blockIdx.x * 256 + threadIdx.x;   // n*512 + p
    int n = id >> 9;
    int p = id & 511;
    int m = n & 63;
    float v0, v1;
    if (n < 64) { v0 = C_re[p * 64 + m]; v1 = -C_im[p * 64 + m]; }
    else        { v0 = C_im[p * 64 + m]; v1 =  C_re[p * 64 + m]; }
    uint32_t h = pack_bf16x2(v0, v1);
    float h0 = __uint_as_float(h << 16);
    float h1 = __uint_as_float(h & 0xFFFF0000u);
    g_Bh[id] = h;
    g_Bl[id] = pack_bf16x2(v0 - h0, v1 - h1);
}

// ---------------- kernel 2: fused 3-pass scan, alpha pipelined ------------
__global__ __launch_bounds__(64) void scan_kernel(
        const float* __restrict__ x,
        const float* __restrict__ lam_re,
        const float* __restrict__ lam_im) {
    int bk = blockIdx.x;              // 0..255
    int b = bk >> 3;
    int k = bk & 7;
    int n = threadIdx.x;              // 0..63
    int kn = (k << 6) | n;

    float lr = lam_re[kn], li = lam_im[kn];
    float2 Bp = g_Bp[kn];
    float2 s1 = make_float2(0.f, 0.f);
    float2 s2 = make_float2(0.f, 0.f);
    float2 s3 = make_float2(0.f, 0.f);
    float p1r = 0.f, p1i = 0.f, p2r = 0.f, p2i = 0.f, p3r = 0.f, p3i = 0.f;
    float a1c = 1.f, a2c = 1.f;

    __shared__ float xs[64];
    const int xoff = b * K_DIM + k;

    for (int tt = 0; tt < T_DIM; tt += 64) {
        __syncthreads();
        int tl = tt + n;
        xs[n] = (tl == 0) ? 0.f : x[(tl - 1) * BK + xoff];
        __syncthreads();
        #pragma unroll 8
        for (int j = 0; j < 64; ++j) {
            float xm1 = xs[j];
            float bxr = Bp.x * xm1, bxi = Bp.y * xm1;
            // state updates use CARRIED p (= lam*s_{t-1}) and a (from pass-1/2 p)
            s3.x = fmaf(a2c, p3r, bxr);  s3.y = fmaf(a2c, p3i, bxi);
            s2.x = fmaf(a1c, p2r, bxr);  s2.y = fmaf(a1c, p2i, bxi);
            s1.x = p1r + bxr;            s1.y = p1i + bxi;
            // prepare next-step products and alphas (off critical path)
            p1r = lr * s1.x - li * s1.y;  p1i = lr * s1.y + li * s1.x;
            p2r = lr * s2.x - li * s2.y;  p2i = lr * s2.y + li * s2.x;
            p3r = lr * s3.x - li * s3.y;  p3i = lr * s3.y + li * s3.x;
            a1c = rsqrtf(1.f + p1r * p1r + p1i * p1i);
            a2c = rsqrtf(1.f + p2r * p2r + p2i * p2i);
            // emit packed bf16 hi/lo
            uint32_t ro = (((tt + j) << 5) + b) * 512 + kn;
            uint32_t h = pack_bf16x2(s3.x, s3.y);
            float hre = __uint_as_float(h << 16);
            float him = __uint_as_float(h & 0xFFFF0000u);
            g_Ahi[ro] = h;
            g_Alo[ro] = pack_bf16x2(s3.x - hre, s3.y - him);
        }
    }
}

// ---------------- kernel 3: mma.sync bf16 GEMM, 3-stage, 1 sync/chunk -----
// CTA 512 thr (16 warps, 8m x 2n), tile 256x128, warp tile 32x64.
// Per chunk: CP_WAIT (my groups) -> __syncthreads (all views + compute done)
//            -> issue kc+2 into buf(kc-1) -> compute kc.
#define SROW 80
#define AH_OFF 0
#define AL_OFF (256 * SROW)               // 20480
#define BH_OFF (2 * 256 * SROW)           // 40960
#define BL_OFF (BH_OFF + 128 * SROW)      // 51200
#define STAGE_BYTES (BL_OFF + 128 * SROW) // 61440
#define NSTAGE 3
#define NCHUNK 32

extern __shared__ uint8_t dynSmem[];

__device__ __forceinline__ void issue_chunk(int kc, uint32_t sbuf, int rowBase,
                                            int grow, int gc) {
    int k0b = kc * 64;   // byte offset of chunk within a 2048B row
    const uint8_t* gAh = (const uint8_t*)g_Ahi;
    const uint8_t* gAl = (const uint8_t*)g_Alo;
    const uint8_t* gBh = (const uint8_t*)g_Bh;
    const uint8_t* gBl = (const uint8_t*)g_Bl;
    #pragma unroll
    for (int i = 0; i < 2; ++i) {
        int row = grow + i * 128;
        size_t ga = (size_t)(rowBase + row) * (KTOT * 2) + k0b + gc * 16;
        uint32_t so = row * SROW + gc * 16;
        CP16(sbuf + AH_OFF + so, gAh + ga);
        CP16(sbuf + AL_OFF + so, gAl + ga);
    }
    {
        size_t gb = (size_t)grow * (KTOT * 2) + k0b + gc * 16;
        uint32_t so = grow * SROW + gc * 16;
        CP16(sbuf + BH_OFF + so, gBh + gb);
        CP16(sbuf + BL_OFF + so, gBl + gb);
    }
}

__global__ __launch_bounds__(512, 1) void gemm_mma(
        const float* __restrict__ x, const float* __restrict__ D,
        const float* __restrict__ Do, float* __restrict__ out, int writeCplx) {
    __shared__ float Ds[512];
    __shared__ float doSum[64];

    int tid = threadIdx.x;
    int wid = tid >> 5, lane = tid & 31;
    int wm = wid & 7, wn = wid >> 3;          // warp grid 8m x 2n
    int rowBase = blockIdx.x * 256;

    if (tid < 512) Ds[tid] = D[tid];
    if (tid < 64) {
        float s = 0.f;
        #pragma unroll
        for (int k = 0; k < K_DIM; ++k) s += Do[k * 64 + tid];
        doSum[tid] = s;
    }

    uint32_t sbase0 = smem_u32(dynSmem);

    // ldmatrix per-thread address components
    int mi = lane >> 3;                        // 0..3
    int arow = (lane & 7) + (mi & 1) * 8;
    int acol16 = mi >> 1;
    int bnrow = (mi >> 1) * 8 + (lane & 7);
    int bk16 = mi & 1;

    float acc[2][8][4];
    #pragma unroll
    for (int mt = 0; mt < 2; ++mt)
        #pragma unroll
        for (int nt = 0; nt < 8; ++nt)
            #pragma unroll
            for (int e = 0; e < 4; ++e) acc[mt][nt][e] = 0.f;

    int grow = tid >> 2, gc = tid & 3;         // grow 0..127

    issue_chunk(0, sbase0, rowBase, grow, gc);
    CP_COMMIT();
    issue_chunk(1, sbase0 + STAGE_BYTES, rowBase, grow, gc);
    CP_COMMIT();

    int buf = 0;                               // buffer index of chunk kc
    #pragma unroll 1
    for (int kc = 0; kc < NCHUNK; ++kc) {
        if (kc + 1 < NCHUNK) { CP_WAIT(1); } else { CP_WAIT(0); }
        __syncthreads();   // all threads: chunk kc landed; compute(kc-1) done
        if (kc + 2 < NCHUNK) {
            int nb = buf + 2; if (nb >= NSTAGE) nb -= NSTAGE;
            issue_chunk(kc + 2, sbase0 + nb * STAGE_BYTES, rowBase, grow, gc);
            CP_COMMIT();
        }

        uint32_t sAh = sbase0 + buf * STAGE_BYTES;
        uint32_t sAl = sAh + AL_OFF;
        uint32_t sBh = sAh + BH_OFF;
        uint32_t sBl = sAh + BL_OFF;

        #pragma unroll
        for (int ks = 0; ks < 2; ++ks) {
            uint32_t ah[2][4], al[2][4];
            #pragma unroll
            for (int mt = 0; mt < 2; ++mt) {
                uint32_t off = (wm * 32 + mt * 16 + arow) * SROW + ks * 32 + acol16 * 16;
                ldsm_x4(ah[mt], sAh + off);
                ldsm_x4(al[mt], sAl + off);
            }
            #pragma unroll
            for (int ntp = 0; ntp < 4; ++ntp) {
                uint32_t boff = (wn * 64 + ntp * 16 + bnrow) * SROW + ks * 32 + bk16 * 16;
                uint32_t bh4[4], bl4[4];
                ldsm_x4(bh4, sBh + boff);
                ldsm_x4(bl4, sBl + boff);
                #pragma unroll
                for (int mt = 0; mt < 2; ++mt) {
                    mma_bf16(acc[mt][2 * ntp],     ah[mt], bh4);
                    mma_bf16(acc[mt][2 * ntp],     al[mt], bh4);
                    mma_bf16(acc[mt][2 * ntp],     ah[mt], bl4);
                    mma_bf16(acc[mt][2 * ntp + 1], ah[mt], bh4 + 2);
                    mma_bf16(acc[mt][2 * ntp + 1], al[mt], bh4 + 2);
                    mma_bf16(acc[mt][2 * ntp + 1], ah[mt], bl4 + 2);
                }
            }
        }
        ++buf; if (buf >= NSTAGE) buf = 0;
    }

    // epilogue
    int gID = lane >> 2, tg = lane & 3;
    #pragma unroll
    for (int mt = 0; mt < 2; ++mt) {
        #pragma unroll
        for (int half = 0; half < 2; ++half) {
            int R = rowBase + wm * 32 + mt * 16 + gID + half * 8;
            float xv[K_DIM];
            #pragma unroll
            for (int k = 0; k < K_DIM; ++k) xv[k] = x[R * K_DIM + k];
            #pragma unroll
            for (int nt = 0; nt < 8; ++nt) {
                #pragma unroll
                for (int e = 0; e < 2; ++e) {
                    int col = wn * 64 + nt * 8 + tg * 2 + e;
                    float a = acc[mt][nt][half * 2 + e];
                    if (wn == 0) {  // real part: add x*D + Do, scale
                        int m = col;
                        float dt = doSum[m];
                        #pragma unroll
                        for (int k = 0; k < K_DIM; ++k)
                            dt = fmaf(xv[k], Ds[k * 64 + m], dt);
                        float v = (a + dt) * 0.125f;
                        if (writeCplx) out[((size_t)R * 64 + m) * 2] = v;
                        else           out[(size_t)R * 64 + m] = v;
                    } else {        // imag part
                        int m = col - 64;
                        if (writeCplx) out[((size_t)R * 64 + m) * 2 + 1] = a * 0.125f;
                    }
                }
            }
        }
    }
}

// ---------------- launch ----------------
extern "C" void kernel_launch(void* const* d_in, const int* in_sizes, int n_in,
                              void* d_out, int out_size) {
    const float* x = nullptr;
    const float* cbuf[2] = {nullptr, nullptr};
    const float* vbuf[4] = {nullptr, nullptr, nullptr, nullptr};
    int nc = 0, nv = 0;
    for (int i = 0; i < n_in; ++i) {
        int sz = in_sizes[i];
        const float* p = (const float*)d_in[i];
        if (sz == X_SZ) x = p;
        else if (sz == C_SZ) { if (nc < 2) cbuf[nc++] = p; }
        else if (sz == V_SZ) { if (nv < 4) vbuf[nv++] = p; }
    }
    if (!x || nc < 2 || nv < 4) return;
    const float* C_re   = cbuf[0];
    const float* C_im   = cbuf[1];
    const float* lam_re = vbuf[0];
    const float* lam_im = vbuf[1];
    const float* D      = vbuf[2];
    const float* Do     = vbuf[3];

    int writeCplx = (out_size >= 2 * OUT_CPLX) ? 1 : 0;

    cudaFuncSetAttribute(gemm_mma, cudaFuncAttributeMaxDynamicSharedMemorySize,
                         NSTAGE * STAGE_BYTES);

    bp_kernel<<<KN, 64>>>(lam_re, lam_im);
    bprep_kernel<<<NTOT * 512 / 256, 256>>>(C_re, C_im);
    scan_kernel<<<BK, N_DIM>>>(x, lam_re, lam_im);
    gemm_mma<<<ROWS / 256, 512, NSTAGE * STAGE_BYTES>>>(x, D, Do, (float*)d_out, writeCplx);
}